// round 1
// baseline (speedup 1.0000x reference)
#include <cuda_runtime.h>

#define NPTS   8192
#define NB     2
#define KNN    10
#define BLOCK  128
#define BPB    (NPTS / BLOCK)   /* 64 blocks per batch  */
#define NBLOCKS (NB * BPB)      /* 128 total blocks     */

__device__ float g_partial[NBLOCKS];

__global__ void __launch_bounds__(BLOCK, 1) knn_lap_kernel(
    const float* __restrict__ p1, const float* __restrict__ p2)
{
    extern __shared__ float4 sp[];   // NPTS * float4(x, y, z, |p|^2) = 128 KB
    const int b = blockIdx.y;
    const float* base1 = p1 + (size_t)b * NPTS * 3;
    const float* base2 = p2 + (size_t)b * NPTS * 3;

    // Stage full batch-b point1 cloud into shared memory.
    for (int j = threadIdx.x; j < NPTS; j += BLOCK) {
        float x = base1[3*j+0];
        float y = base1[3*j+1];
        float z = base1[3*j+2];
        sp[j] = make_float4(x, y, z, fmaf(x, x, fmaf(y, y, z*z)));
    }
    __syncthreads();

    const int qi = blockIdx.x * BLOCK + threadIdx.x;   // query index in [0, NPTS)
    const float4 q = sp[qi];

    // Sorted (ascending) top-K of d2' = |pj|^2 - 2*dot(pi,pj)  (constant |pi|^2 dropped)
    float nd[KNN];
    int   ni[KNN];
#pragma unroll
    for (int t = 0; t < KNN; ++t) { nd[t] = 3.402823466e38f; ni[t] = 0; }

#pragma unroll 8
    for (int j = 0; j < NPTS; ++j) {
        float4 c  = sp[j];                                   // broadcast LDS.128
        float dot = fmaf(q.x, c.x, fmaf(q.y, c.y, q.z * c.z));
        float d2  = fmaf(-2.0f, dot, c.w);
        if (d2 < nd[KNN-1] && j != qi) {                     // rare path
            float cd = d2; int ci = j;
#pragma unroll
            for (int t = KNN-1; t > 0; --t) {
                if (cd >= nd[t-1]) { nd[t] = cd; ni[t] = ci; goto ins_done; }
                nd[t] = nd[t-1]; ni[t] = ni[t-1];
            }
            nd[0] = cd; ni[0] = ci;
            ins_done: ;
        }
    }

    // Uniform Laplacian: mean(neighbors) - point, for both clouds (same knn idx).
    float s1x = 0.f, s1y = 0.f, s1z = 0.f;
    float s2x = 0.f, s2y = 0.f, s2z = 0.f;
#pragma unroll
    for (int t = 0; t < KNN; ++t) {
        float4 c = sp[ni[t]];
        s1x += c.x; s1y += c.y; s1z += c.z;
        const float* pp = base2 + 3 * ni[t];
        s2x += __ldg(pp + 0);
        s2y += __ldg(pp + 1);
        s2z += __ldg(pp + 2);
    }
    float q2x = __ldg(base2 + 3*qi + 0);
    float q2y = __ldg(base2 + 3*qi + 1);
    float q2z = __ldg(base2 + 3*qi + 2);

    const float inv = 1.0f / (float)KNN;
    float acc = fabsf((s1x*inv - q.x) - (s2x*inv - q2x))
              + fabsf((s1y*inv - q.y) - (s2y*inv - q2y))
              + fabsf((s1z*inv - q.z) - (s2z*inv - q2z));

    // Deterministic block reduction (warp shuffle + 4-way smem).
    __syncthreads();                    // done reading sp as point data
    float* sred = (float*)sp;
#pragma unroll
    for (int o = 16; o > 0; o >>= 1)
        acc += __shfl_down_sync(0xffffffffu, acc, o);
    if ((threadIdx.x & 31) == 0) sred[threadIdx.x >> 5] = acc;
    __syncthreads();
    if (threadIdx.x == 0) {
        float s = sred[0] + sred[1] + sred[2] + sred[3];
        g_partial[blockIdx.y * BPB + blockIdx.x] = s;
    }
}

__global__ void finalize_kernel(float* __restrict__ out)
{
    __shared__ float s[NBLOCKS];
    int t = threadIdx.x;
    s[t] = g_partial[t];
    __syncthreads();
#pragma unroll
    for (int o = NBLOCKS / 2; o > 0; o >>= 1) {
        if (t < o) s[t] += s[t + o];
        __syncthreads();
    }
    if (t == 0) out[0] = s[0] * (1.0f / (float)(NB * NPTS * 3));
}

extern "C" void kernel_launch(void* const* d_in, const int* in_sizes, int n_in,
                              void* d_out, int out_size)
{
    (void)in_sizes; (void)n_in; (void)out_size;
    const float* p1 = (const float*)d_in[0];
    const float* p2 = (const float*)d_in[1];

    cudaFuncSetAttribute(knn_lap_kernel,
                         cudaFuncAttributeMaxDynamicSharedMemorySize,
                         NPTS * sizeof(float4));

    dim3 grid(BPB, NB);
    knn_lap_kernel<<<grid, BLOCK, NPTS * sizeof(float4)>>>(p1, p2);
    finalize_kernel<<<1, NBLOCKS>>>((float*)d_out);
}

// round 4
// speedup vs baseline: 1.8329x; 1.8329x over previous
#include <cuda_runtime.h>

#define NPTS   8192
#define NB     2
#define KNN    10
#define QPB    128              /* queries per CTA                   */
#define BLOCK  256              /* 2 threads per query (split halves) */
#define HALF   (NPTS / 2)       /* 4096 candidates per thread        */
#define BPB    (NPTS / QPB)     /* 64 blocks per batch               */
#define NBLOCKS (NB * BPB)      /* 128 total blocks                  */
#define VEC    8                /* candidates per branch-check block */

#define SMEM_SP_BYTES   (NPTS * 16)                       /* 131072 */
#define SMEM_ND_BYTES   (QPB * KNN * 4)                   /* 5120   */
#define SMEM_TOTAL      (SMEM_SP_BYTES + 2 * SMEM_ND_BYTES)

__device__ float g_partial[NBLOCKS];

__global__ void dummy_kernel() {}

__global__ void __launch_bounds__(BLOCK, 1) knn_lap_kernel(
    const float* __restrict__ p1, const float* __restrict__ p2)
{
    extern __shared__ char smem_raw[];
    float4* sp  = (float4*)smem_raw;                       // 8192 * float4 = 128 KB
    float*  snd = (float*)(smem_raw + SMEM_SP_BYTES);      // upper-half top-K dists
    int*    sni = (int*)(smem_raw + SMEM_SP_BYTES + SMEM_ND_BYTES);

    const int b = blockIdx.y;
    const float* base1 = p1 + (size_t)b * NPTS * 3;
    const float* base2 = p2 + (size_t)b * NPTS * 3;

    // Stage full batch-b point1 cloud into shared memory as (x,y,z,|p|^2).
    for (int j = threadIdx.x; j < NPTS; j += BLOCK) {
        float x = base1[3*j+0];
        float y = base1[3*j+1];
        float z = base1[3*j+2];
        sp[j] = make_float4(x, y, z, fmaf(x, x, fmaf(y, y, z*z)));
    }
    __syncthreads();

    const int tq   = threadIdx.x & (QPB - 1);   // query slot within CTA
    const int half = threadIdx.x >> 7;          // 0: j in [0,4096), 1: [4096,8192)
    const int qi   = blockIdx.x * QPB + tq;     // global query index
    const float4 q = sp[qi];

    // Sorted (ascending) top-K of d2' = |pj|^2 - 2*dot(pi,pj) over this half.
    float nd[KNN];
    int   ni[KNN];
#pragma unroll
    for (int t = 0; t < KNN; ++t) { nd[t] = 3.402823466e38f; ni[t] = 0; }
    float thresh = 3.402823466e38f;

    const int jbeg = half * HALF;
    const int jend = jbeg + HALF;
    for (int j0 = jbeg; j0 < jend; j0 += VEC) {
        // Branchless: VEC independent LDS.128(broadcast) + FMA chains.
        float d2[VEC];
#pragma unroll
        for (int u = 0; u < VEC; ++u) {
            float4 c = sp[j0 + u];
            float dot = fmaf(q.x, c.x, fmaf(q.y, c.y, q.z * c.z));
            d2[u] = fmaf(-2.0f, dot, c.w);
        }
        float m0 = fminf(d2[0], d2[1]);
        float m1 = fminf(d2[2], d2[3]);
        float m2 = fminf(d2[4], d2[5]);
        float m3 = fminf(d2[6], d2[7]);
        float mn = fminf(fminf(m0, m1), fminf(m2, m3));

        if (mn < thresh) {       // one branch per VEC candidates (rare past warmup)
#pragma unroll
            for (int u = 0; u < VEC; ++u) {
                if (d2[u] < thresh) {
                    int j = j0 + u;
                    if (j != qi) {
                        float cd = d2[u]; int ci = j;
#pragma unroll
                        for (int t = KNN-1; t > 0; --t) {
                            if (cd >= nd[t-1]) { nd[t] = cd; ni[t] = ci; goto ins_done; }
                            nd[t] = nd[t-1]; ni[t] = ni[t-1];
                        }
                        nd[0] = cd; ni[0] = ci;
                        ins_done: ;
                        thresh = nd[KNN-1];
                    }
                }
            }
        }
    }

    // Upper half publishes its sorted lists; lower half merges (2x sorted 10 -> 10).
    if (half == 1) {
#pragma unroll
        for (int t = 0; t < KNN; ++t) {
            snd[tq * KNN + t] = nd[t];
            sni[tq * KNN + t] = ni[t];
        }
    }
    __syncthreads();

    float acc = 0.0f;
    if (half == 0) {
        float md[KNN]; int mi[KNN];
        int a = 0, bidx = 0;
#pragma unroll
        for (int t = 0; t < KNN; ++t) {
            float av = nd[a];
            float bv = snd[tq * KNN + bidx];
            if (av <= bv) { md[t] = av; mi[t] = ni[a]; ++a; }
            else          { md[t] = bv; mi[t] = sni[tq * KNN + bidx]; ++bidx; }
        }

        // Uniform Laplacian: mean(neighbors) - point, both clouds, same indices.
        float s1x = 0.f, s1y = 0.f, s1z = 0.f;
        float s2x = 0.f, s2y = 0.f, s2z = 0.f;
#pragma unroll
        for (int t = 0; t < KNN; ++t) {
            float4 c = sp[mi[t]];
            s1x += c.x; s1y += c.y; s1z += c.z;
            const float* pp = base2 + 3 * mi[t];
            s2x += __ldg(pp + 0);
            s2y += __ldg(pp + 1);
            s2z += __ldg(pp + 2);
        }
        float q2x = __ldg(base2 + 3*qi + 0);
        float q2y = __ldg(base2 + 3*qi + 1);
        float q2z = __ldg(base2 + 3*qi + 2);

        const float inv = 1.0f / (float)KNN;
        acc = fabsf((s1x*inv - q.x) - (s2x*inv - q2x))
            + fabsf((s1y*inv - q.y) - (s2y*inv - q2y))
            + fabsf((s1z*inv - q.z) - (s2z*inv - q2z));
    }

    // Deterministic block reduction over all 8 warps (upper warps contribute 0).
    __syncthreads();
    __shared__ float sred[BLOCK / 32];
#pragma unroll
    for (int o = 16; o > 0; o >>= 1)
        acc += __shfl_down_sync(0xffffffffu, acc, o);
    if ((threadIdx.x & 31) == 0) sred[threadIdx.x >> 5] = acc;
    __syncthreads();
    if (threadIdx.x == 0) {
        float s = 0.f;
#pragma unroll
        for (int w = 0; w < BLOCK / 32; ++w) s += sred[w];
        g_partial[blockIdx.y * BPB + blockIdx.x] = s;
    }
}

__global__ void finalize_kernel(float* __restrict__ out)
{
    __shared__ float s[NBLOCKS];
    int t = threadIdx.x;
    s[t] = g_partial[t];
    __syncthreads();
#pragma unroll
    for (int o = NBLOCKS / 2; o > 0; o >>= 1) {
        if (t < o) s[t] += s[t + o];
        __syncthreads();
    }
    if (t == 0) out[0] = s[0] * (1.0f / (float)(NB * NPTS * 3));
}

extern "C" void kernel_launch(void* const* d_in, const int* in_sizes, int n_in,
                              void* d_out, int out_size)
{
    (void)in_sizes; (void)n_in; (void)out_size;
    const float* p1 = (const float*)d_in[0];
    const float* p2 = (const float*)d_in[1];

    cudaFuncSetAttribute(knn_lap_kernel,
                         cudaFuncAttributeMaxDynamicSharedMemorySize,
                         SMEM_TOTAL);

    // 5 no-op launches so ncu (-s 5 -c 1) profiles the main kernel, not finalize.
    for (int i = 0; i < 5; ++i) dummy_kernel<<<1, 32>>>();

    dim3 grid(BPB, NB);
    knn_lap_kernel<<<grid, BLOCK, SMEM_TOTAL>>>(p1, p2);
    finalize_kernel<<<1, NBLOCKS>>>((float*)d_out);
}

// round 5
// speedup vs baseline: 2.2057x; 1.2034x over previous
#include <cuda_runtime.h>

#define NPTS   8192
#define NB     2
#define KNN    10
#define QPB    128              /* queries per CTA                   */
#define BLOCK  256              /* 2 threads per query (split halves) */
#define HALF   (NPTS / 2)       /* 4096 candidates per thread        */
#define BPB    (NPTS / QPB)     /* 64 blocks per batch               */
#define NBLOCKS (NB * BPB)      /* 128 total blocks                  */
#define VEC    8                /* candidates per branch-check block */
#define FLT_BIG 3.402823466e38f

#define SMEM_SP_BYTES   (NPTS * 16)                       /* 131072 */
#define SMEM_ND_BYTES   (QPB * KNN * 4)                   /* 5120   */
#define SMEM_TOTAL      (SMEM_SP_BYTES + 2 * SMEM_ND_BYTES)

__device__ float g_partial[NBLOCKS];

__global__ void dummy_kernel() {}

__global__ void __launch_bounds__(BLOCK, 1) knn_lap_kernel(
    const float* __restrict__ p1, const float* __restrict__ p2)
{
    extern __shared__ char smem_raw[];
    float4* sp  = (float4*)smem_raw;                       // 8192 * float4 = 128 KB
    float*  snd = (float*)(smem_raw + SMEM_SP_BYTES);      // upper-half top-K dists
    int*    sni = (int*)(smem_raw + SMEM_SP_BYTES + SMEM_ND_BYTES);

    const int b = blockIdx.y;
    const float* base1 = p1 + (size_t)b * NPTS * 3;
    const float* base2 = p2 + (size_t)b * NPTS * 3;

    // Stage full batch-b point1 cloud into shared memory as (x,y,z,|p|^2).
    for (int j = threadIdx.x; j < NPTS; j += BLOCK) {
        float x = base1[3*j+0];
        float y = base1[3*j+1];
        float z = base1[3*j+2];
        sp[j] = make_float4(x, y, z, fmaf(x, x, fmaf(y, y, z*z)));
    }
    __syncthreads();

    const int tq   = threadIdx.x & (QPB - 1);   // query slot within CTA
    const int half = threadIdx.x >> 7;          // 0: j in [0,4096), 1: [4096,8192)
    const int qi   = blockIdx.x * QPB + tq;     // global query index
    const float4 q = sp[qi];

    // Sorted (ascending) top-K of d2' = |pj|^2 - 2*dot(pi,pj) over this half.
    float nd[KNN];
    int   ni[KNN];
#pragma unroll
    for (int t = 0; t < KNN; ++t) { nd[t] = FLT_BIG; ni[t] = 0; }
    float thresh = FLT_BIG;

    const int jbeg = half * HALF;
    const int jend = jbeg + HALF;
    for (int j0 = jbeg; j0 < jend; j0 += VEC) {
        // Fast path: VEC independent LDS.128(broadcast) + FMA chains.
        float d2[VEC];
#pragma unroll
        for (int u = 0; u < VEC; ++u) {
            float4 c = sp[j0 + u];
            float dot = fmaf(q.x, c.x, fmaf(q.y, c.y, q.z * c.z));
            d2[u] = fmaf(-2.0f, dot, c.w);
        }
        float m0 = fminf(d2[0], d2[1]);
        float m1 = fminf(d2[2], d2[3]);
        float m2 = fminf(d2[4], d2[5]);
        float m3 = fminf(d2[6], d2[7]);
        float mn = fminf(fminf(m0, m1), fminf(m2, m3));

        if (mn < thresh) {     // warp-coherent prescreen, one branch per 8 cands
#pragma unroll
            for (int u = 0; u < VEC; ++u) {
                if (d2[u] < thresh) {
                    const int j = j0 + u;
                    // Self-predicating branchless insertion network.
                    // If cd >= nd[KNN-1] every select is identity (no-op).
                    const float cd = (j == qi) ? FLT_BIG : d2[u];
                    const int   ci = j;
                    bool bt = cd < nd[KNN-1];
#pragma unroll
                    for (int t = KNN-1; t >= 1; --t) {
                        bool btm = cd < nd[t-1];
                        nd[t] = bt ? (btm ? nd[t-1] : cd) : nd[t];
                        ni[t] = bt ? (btm ? ni[t-1] : ci) : ni[t];
                        bt = btm;
                    }
                    nd[0] = bt ? cd : nd[0];
                    ni[0] = bt ? ci : ni[0];
                    thresh = nd[KNN-1];
                }
            }
        }
    }

    // Upper half publishes its sorted lists; lower half merges (2x sorted 10 -> 10).
    if (half == 1) {
#pragma unroll
        for (int t = 0; t < KNN; ++t) {
            snd[tq * KNN + t] = nd[t];
            sni[tq * KNN + t] = ni[t];
        }
    }
    __syncthreads();

    float acc = 0.0f;
    if (half == 0) {
        float md[KNN]; int mi[KNN];
        int a = 0, bidx = 0;
#pragma unroll
        for (int t = 0; t < KNN; ++t) {
            float av = nd[a];
            float bv = snd[tq * KNN + bidx];
            if (av <= bv) { md[t] = av; mi[t] = ni[a]; ++a; }
            else          { md[t] = bv; mi[t] = sni[tq * KNN + bidx]; ++bidx; }
        }

        // Uniform Laplacian: mean(neighbors) - point, both clouds, same indices.
        float s1x = 0.f, s1y = 0.f, s1z = 0.f;
        float s2x = 0.f, s2y = 0.f, s2z = 0.f;
#pragma unroll
        for (int t = 0; t < KNN; ++t) {
            float4 c = sp[mi[t]];
            s1x += c.x; s1y += c.y; s1z += c.z;
            const float* pp = base2 + 3 * mi[t];
            s2x += __ldg(pp + 0);
            s2y += __ldg(pp + 1);
            s2z += __ldg(pp + 2);
        }
        float q2x = __ldg(base2 + 3*qi + 0);
        float q2y = __ldg(base2 + 3*qi + 1);
        float q2z = __ldg(base2 + 3*qi + 2);

        const float inv = 1.0f / (float)KNN;
        acc = fabsf((s1x*inv - q.x) - (s2x*inv - q2x))
            + fabsf((s1y*inv - q.y) - (s2y*inv - q2y))
            + fabsf((s1z*inv - q.z) - (s2z*inv - q2z));
    }

    // Deterministic block reduction over all 8 warps (upper warps contribute 0).
    __syncthreads();
    __shared__ float sred[BLOCK / 32];
#pragma unroll
    for (int o = 16; o > 0; o >>= 1)
        acc += __shfl_down_sync(0xffffffffu, acc, o);
    if ((threadIdx.x & 31) == 0) sred[threadIdx.x >> 5] = acc;
    __syncthreads();
    if (threadIdx.x == 0) {
        float s = 0.f;
#pragma unroll
        for (int w = 0; w < BLOCK / 32; ++w) s += sred[w];
        g_partial[blockIdx.y * BPB + blockIdx.x] = s;
    }
}

__global__ void finalize_kernel(float* __restrict__ out)
{
    __shared__ float s[NBLOCKS];
    int t = threadIdx.x;
    s[t] = g_partial[t];
    __syncthreads();
#pragma unroll
    for (int o = NBLOCKS / 2; o > 0; o >>= 1) {
        if (t < o) s[t] += s[t + o];
        __syncthreads();
    }
    if (t == 0) out[0] = s[0] * (1.0f / (float)(NB * NPTS * 3));
}

extern "C" void kernel_launch(void* const* d_in, const int* in_sizes, int n_in,
                              void* d_out, int out_size)
{
    (void)in_sizes; (void)n_in; (void)out_size;
    const float* p1 = (const float*)d_in[0];
    const float* p2 = (const float*)d_in[1];

    cudaFuncSetAttribute(knn_lap_kernel,
                         cudaFuncAttributeMaxDynamicSharedMemorySize,
                         SMEM_TOTAL);

    // 4 no-op launches: with the one extra stream launch observed ahead of us,
    // ncu (-s 5 -c 1) should now land on knn_lap_kernel.
    for (int i = 0; i < 4; ++i) dummy_kernel<<<1, 32>>>();

    dim3 grid(BPB, NB);
    knn_lap_kernel<<<grid, BLOCK, SMEM_TOTAL>>>(p1, p2);
    finalize_kernel<<<1, NBLOCKS>>>((float*)d_out);
}

// round 8
// speedup vs baseline: 5.0666x; 2.2970x over previous
#include <cuda_runtime.h>

#define NPTS   8192
#define NB     2
#define KNN    10
#define K2     11               /* KNN + self slot                    */
#define QPB    128              /* queries per CTA                    */
#define SPLIT  4                /* threads per query                  */
#define BLOCK  (QPB * SPLIT)    /* 512                                */
#define LSUB   (NPTS / SPLIT)   /* 2048 candidates per thread         */
#define BPB    (NPTS / QPB)     /* 64 blocks per batch                */
#define NBLOCKS (NB * BPB)      /* 128 total blocks                   */
#define VEC    8

#define SMEM_SP_BYTES  (NPTS * 16)                        /* 131072 */
#define SMEM_LIST_U32  (QPB * (SPLIT - 1) * K2)           /* 4224   */
#define SMEM_TOTAL     (SMEM_SP_BYTES + SMEM_LIST_U32 * 4)

__device__ float g_partial[NBLOCKS];

__device__ __forceinline__ void net_insert(unsigned nd[K2], unsigned ck)
{
    bool tk[K2];
#pragma unroll
    for (int t = 0; t < K2; ++t) tk[t] = ck < nd[t];
#pragma unroll
    for (int t = K2 - 1; t >= 1; --t)
        nd[t] = tk[t] ? (tk[t-1] ? nd[t-1] : ck) : nd[t];
    nd[0] = tk[0] ? ck : nd[0];
}

__global__ void __launch_bounds__(BLOCK, 1) knn_lap_kernel(
    const float* __restrict__ p1, const float* __restrict__ p2)
{
    extern __shared__ char smem_raw[];
    float4*   sp    = (float4*)smem_raw;                  // 8192 * 16B = 128 KB
    unsigned* slist = (unsigned*)(smem_raw + SMEM_SP_BYTES);

    const int b = blockIdx.y;
    const float* base1 = p1 + (size_t)b * NPTS * 3;
    const float* base2 = p2 + (size_t)b * NPTS * 3;

    // Stage full batch-b point1 cloud into shared memory as (x,y,z,|p|^2).
    for (int j = threadIdx.x; j < NPTS; j += BLOCK) {
        float x = base1[3*j+0];
        float y = base1[3*j+1];
        float z = base1[3*j+2];
        sp[j] = make_float4(x, y, z, fmaf(x, x, fmaf(y, y, z*z)));
    }
    __syncthreads();

    const int tq  = threadIdx.x & (QPB - 1);   // query slot within CTA
    const int sub = threadIdx.x >> 7;          // substream 0..3
    const int qi  = blockIdx.x * QPB + tq;     // global query index
    const float4 q = sp[qi];
    const float n2x = -2.0f * q.x, n2y = -2.0f * q.y, n2z = -2.0f * q.z;
    const float qw  = q.w;

    // K2-smallest keys over this substream. key = bits(full d^2) with low 13
    // mantissa bits replaced by candidate index (keys unique, order ~ distance).
    // Self has d^2 == 0 exactly -> key == qi -> always global min.
    unsigned nd[K2];
#pragma unroll
    for (int t = 0; t < K2; ++t) nd[t] = 0xFFFFFFFFu;
    unsigned thresh = 0xFFFFFFFFu;

    const int jbeg = sub * LSUB;
    const int jend = jbeg + LSUB;
    for (int j0 = jbeg; j0 < jend; j0 += VEC) {
        unsigned key[VEC];
#pragma unroll
        for (int u = 0; u < VEC; ++u) {
            float4 c = sp[j0 + u];
            float d2 = fmaf(n2x, c.x, fmaf(n2y, c.y, fmaf(n2z, c.z, c.w + qw)));
            d2 = fmaxf(d2, 0.0f);
            key[u] = (__float_as_uint(d2) & 0xFFFFE000u) | (unsigned)(j0 + u);
        }
        unsigned m0 = min(key[0], key[1]);
        unsigned m1 = min(key[2], key[3]);
        unsigned m2 = min(key[4], key[5]);
        unsigned m3 = min(key[6], key[7]);
        unsigned mn = min(min(m0, m1), min(m2, m3));

        while (mn < thresh) {            // ~1 trip per warp-insert event
            net_insert(nd, mn);
            thresh = nd[K2-1];
#pragma unroll
            for (int u = 0; u < VEC; ++u)         // mask inserted key (unique)
                key[u] = (key[u] == mn) ? 0xFFFFFFFFu : key[u];
            m0 = min(key[0], key[1]);
            m1 = min(key[2], key[3]);
            m2 = min(key[4], key[5]);
            m3 = min(key[6], key[7]);
            mn = min(min(m0, m1), min(m2, m3));
        }
    }

    // Substreams 1..3 publish; substream 0 merges 3*K2 foreign keys.
    if (sub) {
#pragma unroll
        for (int t = 0; t < K2; ++t)
            slist[((sub - 1) * QPB + tq) * K2 + t] = nd[t];
    }
    __syncthreads();

    float acc = 0.0f;
    if (sub == 0) {
        for (int s = 0; s < SPLIT - 1; ++s)
#pragma unroll
            for (int t = 0; t < K2; ++t) {
                unsigned ck = slist[(s * QPB + tq) * K2 + t];
                if (ck < nd[K2-1]) net_insert(nd, ck);
            }

        // nd[0..10] = 11 nearest incl. self. Skip self by index at readout.
        float s1x = 0.f, s1y = 0.f, s1z = 0.f;
        float s2x = 0.f, s2y = 0.f, s2z = 0.f;
#pragma unroll
        for (int t = 0; t < K2; ++t) {
            int idx = (int)(nd[t] & 0x1FFFu);
            if (idx != qi) {
                float4 c = sp[idx];
                s1x += c.x; s1y += c.y; s1z += c.z;
                const float* pp = base2 + 3 * idx;
                s2x += __ldg(pp + 0);
                s2y += __ldg(pp + 1);
                s2z += __ldg(pp + 2);
            }
        }
        float q2x = __ldg(base2 + 3*qi + 0);
        float q2y = __ldg(base2 + 3*qi + 1);
        float q2z = __ldg(base2 + 3*qi + 2);

        const float inv = 1.0f / (float)KNN;
        acc = fabsf((s1x*inv - q.x) - (s2x*inv - q2x))
            + fabsf((s1y*inv - q.y) - (s2y*inv - q2y))
            + fabsf((s1z*inv - q.z) - (s2z*inv - q2z));
    }

    // Deterministic block reduction over 16 warps (non-owner lanes carry 0).
    __syncthreads();
    __shared__ float sred[BLOCK / 32];
#pragma unroll
    for (int o = 16; o > 0; o >>= 1)
        acc += __shfl_down_sync(0xffffffffu, acc, o);
    if ((threadIdx.x & 31) == 0) sred[threadIdx.x >> 5] = acc;
    __syncthreads();
    if (threadIdx.x == 0) {
        float s = 0.f;
#pragma unroll
        for (int w = 0; w < BLOCK / 32; ++w) s += sred[w];
        g_partial[blockIdx.y * BPB + blockIdx.x] = s;
    }
}

__global__ void finalize_kernel(float* __restrict__ out)
{
    __shared__ float s[NBLOCKS];
    int t = threadIdx.x;
    s[t] = g_partial[t];
    __syncthreads();
#pragma unroll
    for (int o = NBLOCKS / 2; o > 0; o >>= 1) {
        if (t < o) s[t] += s[t + o];
        __syncthreads();
    }
    if (t == 0) out[0] = s[0] * (1.0f / (float)(NB * NPTS * 3));
}

extern "C" void kernel_launch(void* const* d_in, const int* in_sizes, int n_in,
                              void* d_out, int out_size)
{
    (void)in_sizes; (void)n_in; (void)out_size;
    const float* p1 = (const float*)d_in[0];
    const float* p2 = (const float*)d_in[1];

    cudaFuncSetAttribute(knn_lap_kernel,
                         cudaFuncAttributeMaxDynamicSharedMemorySize,
                         SMEM_TOTAL);

    dim3 grid(BPB, NB);
    knn_lap_kernel<<<grid, BLOCK, SMEM_TOTAL>>>(p1, p2);
    finalize_kernel<<<1, NBLOCKS>>>((float*)d_out);
}